// round 2
// baseline (speedup 1.0000x reference)
#include <cuda_runtime.h>
#include <float.h>

// ---------------------------------------------------------------------------
// Global min/max scratch: monotonically-mapped fp32 stored as uint so that
// unsigned atomicMin/atomicMax implement float min/max exactly.
//   map:  f >= 0 -> bits | 0x80000000 ; f < 0 -> ~bits    (strictly increasing)
// ---------------------------------------------------------------------------
__device__ unsigned int g_mm[2];   // [0] = mapped min, [1] = mapped max

__device__ __forceinline__ unsigned int fmap(float f) {
    unsigned int u = __float_as_uint(f);
    return (u & 0x80000000u) ? ~u : (u | 0x80000000u);
}
__device__ __forceinline__ float funmap(unsigned int u) {
    u = (u & 0x80000000u) ? (u & 0x7FFFFFFFu) : ~u;
    return __uint_as_float(u);
}

__global__ void mm_init_kernel() {
    g_mm[0] = 0xFFFFFFFFu;   // +inf in mapped space (min identity)
    g_mm[1] = 0x00000000u;   // -inf in mapped space (max identity)
}

// ---------------------------------------------------------------------------
// Pass 1: grid-stride min/max reduction, 4 x float4 per iteration (MLP=4).
// ---------------------------------------------------------------------------
__global__ void __launch_bounds__(256)
mm_reduce_kernel(const float4* __restrict__ x4, int n4,
                 const float* __restrict__ x, int n) {
    float mn =  FLT_MAX;
    float mx = -FLT_MAX;

    const int stride = gridDim.x * blockDim.x;
    const int gtid = blockIdx.x * blockDim.x + threadIdx.x;

    // Batched main loop: 4 independent float4 loads in flight per iteration.
    int i = gtid;
    for (; i + 3 * stride < n4; i += 4 * stride) {
        float4 a = x4[i];
        float4 b = x4[i + stride];
        float4 c = x4[i + 2 * stride];
        float4 d = x4[i + 3 * stride];
        mn = fminf(mn, fminf(fminf(a.x, a.y), fminf(a.z, a.w)));
        mx = fmaxf(mx, fmaxf(fmaxf(a.x, a.y), fmaxf(a.z, a.w)));
        mn = fminf(mn, fminf(fminf(b.x, b.y), fminf(b.z, b.w)));
        mx = fmaxf(mx, fmaxf(fmaxf(b.x, b.y), fmaxf(b.z, b.w)));
        mn = fminf(mn, fminf(fminf(c.x, c.y), fminf(c.z, c.w)));
        mx = fmaxf(mx, fmaxf(fmaxf(c.x, c.y), fmaxf(c.z, c.w)));
        mn = fminf(mn, fminf(fminf(d.x, d.y), fminf(d.z, d.w)));
        mx = fmaxf(mx, fmaxf(fmaxf(d.x, d.y), fmaxf(d.z, d.w)));
    }
    for (; i < n4; i += stride) {
        float4 v = x4[i];
        mn = fminf(mn, fminf(fminf(v.x, v.y), fminf(v.z, v.w)));
        mx = fmaxf(mx, fmaxf(fmaxf(v.x, v.y), fmaxf(v.z, v.w)));
    }
    // Scalar tail (n not multiple of 4): first few global threads pick it up.
    int base = n4 << 2;
    if (gtid < (n - base)) {
        float v = x[base + gtid];
        mn = fminf(mn, v);
        mx = fmaxf(mx, v);
    }

    // Warp reduce
    #pragma unroll
    for (int o = 16; o > 0; o >>= 1) {
        mn = fminf(mn, __shfl_xor_sync(0xFFFFFFFFu, mn, o));
        mx = fmaxf(mx, __shfl_xor_sync(0xFFFFFFFFu, mx, o));
    }

    __shared__ float smn[8], smx[8];
    int w = threadIdx.x >> 5;
    int l = threadIdx.x & 31;
    if (l == 0) { smn[w] = mn; smx[w] = mx; }
    __syncthreads();

    if (w == 0) {
        int nwarps = (blockDim.x + 31) >> 5;
        mn = (l < nwarps) ? smn[l] :  FLT_MAX;
        mx = (l < nwarps) ? smx[l] : -FLT_MAX;
        #pragma unroll
        for (int o = 4; o > 0; o >>= 1) {
            mn = fminf(mn, __shfl_xor_sync(0xFFFFFFFFu, mn, o));
            mx = fmaxf(mx, __shfl_xor_sync(0xFFFFFFFFu, mx, o));
        }
        if (l == 0) {
            atomicMin(&g_mm[0], fmap(mn));
            atomicMax(&g_mm[1], fmap(mx));
        }
    }
}

// ---------------------------------------------------------------------------
// Pass 2: quantize-dequantize.
//   idx = clip(floor((x - mn)/step), 0, 255);  out = mn + (idx + 0.5)*step
// Fast path uses q = d * (1/step) (reciprocal precomputed with one IEEE
// divide per thread). If q lands within 2e-4 of a bin boundary, redo with an
// exact __fdiv_rn so floor() matches the reference's IEEE divide bitwise.
// Mul-vs-div relative gap <= ~2.5 ulp (~7.6e-5 abs at q<=256), so all
// non-boundary elements are guaranteed identical; boundary elements
// (~4e-4 of all) take one divide each.
// ---------------------------------------------------------------------------
__device__ __forceinline__ float quant1(float x, float mn, float step, float inv) {
    float d = x - mn;                 // >= 0 exactly
    float q = d * inv;
    float t = floorf(q);
    float frac = q - t;
    if (frac < 2e-4f || frac > 0.9998f) {
        q = __fdiv_rn(d, step);       // exact IEEE divide, matches reference
        t = floorf(q);
    }
    t = fmaxf(t, 0.0f);
    t = fminf(t, 255.0f);
    return mn + (t + 0.5f) * step;
}

__device__ __forceinline__ float4 quant4(float4 v, float mn, float step, float inv) {
    float4 r;
    r.x = quant1(v.x, mn, step, inv);
    r.y = quant1(v.y, mn, step, inv);
    r.z = quant1(v.z, mn, step, inv);
    r.w = quant1(v.w, mn, step, inv);
    return r;
}

__global__ void __launch_bounds__(256)
quant_kernel(const float4* __restrict__ x4, float4* __restrict__ o4, int n4,
             const float* __restrict__ x, float* __restrict__ o, int n) {
    float mn = funmap(g_mm[0]);
    float mx = funmap(g_mm[1]);
    // Reference: step = (max - min) / 256 ; /256 is exact, so *(1/256) matches.
    float step = (mx - mn) * (1.0f / 256.0f);
    float inv  = __fdiv_rn(1.0f, step);

    const int stride = gridDim.x * blockDim.x;
    const int gtid = blockIdx.x * blockDim.x + threadIdx.x;

    // Batched main loop: 4 independent LDG.128 in flight per iteration.
    int i = gtid;
    for (; i + 3 * stride < n4; i += 4 * stride) {
        float4 a = x4[i];
        float4 b = x4[i + stride];
        float4 c = x4[i + 2 * stride];
        float4 d = x4[i + 3 * stride];
        o4[i]              = quant4(a, mn, step, inv);
        o4[i + stride]     = quant4(b, mn, step, inv);
        o4[i + 2 * stride] = quant4(c, mn, step, inv);
        o4[i + 3 * stride] = quant4(d, mn, step, inv);
    }
    for (; i < n4; i += stride) {
        o4[i] = quant4(x4[i], mn, step, inv);
    }
    int base = n4 << 2;
    if (gtid < (n - base)) {
        o[base + gtid] = quant1(x[base + gtid], mn, step, inv);
    }
}

// ---------------------------------------------------------------------------
// Launch
// ---------------------------------------------------------------------------
extern "C" void kernel_launch(void* const* d_in, const int* in_sizes, int n_in,
                              void* d_out, int out_size) {
    const float* x = (const float*)d_in[0];
    float* out = (float*)d_out;
    const int n  = in_sizes[0];
    const int n4 = n >> 2;

    const int threads = 256;
    int blocks = (n4 + threads - 1) / threads;
    int blocks_r = blocks > 1184 ? 1184 : (blocks < 1 ? 1 : blocks);  // 148 SMs * 8
    int blocks_q = blocks > 2368 ? 2368 : (blocks < 1 ? 1 : blocks);  // 148 SMs * 16

    mm_init_kernel<<<1, 1>>>();
    mm_reduce_kernel<<<blocks_r, threads>>>((const float4*)x, n4, x, n);
    quant_kernel<<<blocks_q, threads>>>((const float4*)x, (float4*)out, n4, x, out, n);
}

// round 4
// speedup vs baseline: 1.0289x; 1.0289x over previous
#include <cuda_runtime.h>
#include <float.h>

// ---------------------------------------------------------------------------
// Per-block partial min/max. Written unconditionally by every reduce block,
// so no initialization kernel is needed (saves a 3.3us 1-thread launch).
// ---------------------------------------------------------------------------
#define MAX_PARTIALS 1184          // 148 SMs * 8 CTAs cap on reduce grid
__device__ float g_pmn[MAX_PARTIALS];
__device__ float g_pmx[MAX_PARTIALS];

// ---------------------------------------------------------------------------
// Pass 1: grid-stride min/max reduction, 4 x float4 per iteration (MLP=4).
// Each block writes one (min, max) partial.
// ---------------------------------------------------------------------------
__global__ void __launch_bounds__(256)
mm_reduce_kernel(const float4* __restrict__ x4, int n4,
                 const float* __restrict__ x, int n) {
    float mn =  FLT_MAX;
    float mx = -FLT_MAX;

    const int stride = gridDim.x * blockDim.x;
    const int gtid = blockIdx.x * blockDim.x + threadIdx.x;

    int i = gtid;
    for (; i + 3 * stride < n4; i += 4 * stride) {
        float4 a = __ldcs(&x4[i]);
        float4 b = __ldcs(&x4[i + stride]);
        float4 c = __ldcs(&x4[i + 2 * stride]);
        float4 d = __ldcs(&x4[i + 3 * stride]);
        mn = fminf(mn, fminf(fminf(a.x, a.y), fminf(a.z, a.w)));
        mx = fmaxf(mx, fmaxf(fmaxf(a.x, a.y), fmaxf(a.z, a.w)));
        mn = fminf(mn, fminf(fminf(b.x, b.y), fminf(b.z, b.w)));
        mx = fmaxf(mx, fmaxf(fmaxf(b.x, b.y), fmaxf(b.z, b.w)));
        mn = fminf(mn, fminf(fminf(c.x, c.y), fminf(c.z, c.w)));
        mx = fmaxf(mx, fmaxf(fmaxf(c.x, c.y), fmaxf(c.z, c.w)));
        mn = fminf(mn, fminf(fminf(d.x, d.y), fminf(d.z, d.w)));
        mx = fmaxf(mx, fmaxf(fmaxf(d.x, d.y), fmaxf(d.z, d.w)));
    }
    for (; i < n4; i += stride) {
        float4 v = __ldcs(&x4[i]);
        mn = fminf(mn, fminf(fminf(v.x, v.y), fminf(v.z, v.w)));
        mx = fmaxf(mx, fmaxf(fmaxf(v.x, v.y), fmaxf(v.z, v.w)));
    }
    // Scalar tail (n not multiple of 4).
    int base = n4 << 2;
    if (gtid < (n - base)) {
        float v = x[base + gtid];
        mn = fminf(mn, v);
        mx = fmaxf(mx, v);
    }

    // Warp reduce
    #pragma unroll
    for (int o = 16; o > 0; o >>= 1) {
        mn = fminf(mn, __shfl_xor_sync(0xFFFFFFFFu, mn, o));
        mx = fmaxf(mx, __shfl_xor_sync(0xFFFFFFFFu, mx, o));
    }

    __shared__ float smn[8], smx[8];
    int w = threadIdx.x >> 5;
    int l = threadIdx.x & 31;
    if (l == 0) { smn[w] = mn; smx[w] = mx; }
    __syncthreads();

    if (w == 0) {
        mn = (l < 8) ? smn[l] :  FLT_MAX;
        mx = (l < 8) ? smx[l] : -FLT_MAX;
        #pragma unroll
        for (int o = 4; o > 0; o >>= 1) {
            mn = fminf(mn, __shfl_xor_sync(0xFFFFFFFFu, mn, o));
            mx = fmaxf(mx, __shfl_xor_sync(0xFFFFFFFFu, mx, o));
        }
        if (l == 0) {
            g_pmn[blockIdx.x] = mn;
            g_pmx[blockIdx.x] = mx;
        }
    }
}

// ---------------------------------------------------------------------------
// Pass 2: quantize-dequantize.
//   idx = clip(floor((x - mn)/step), 0, 255);  out = mn + (idx + 0.5)*step
// Prologue: every block redundantly reduces the <=1184 partials (L2-hit,
// ~5 loads/thread) to recover the exact global min/max.
// Fast path uses q = d * (1/step); if q lands within 2e-4 of a bin boundary,
// redo with an exact __fdiv_rn so floor() matches the reference's IEEE
// divide bitwise. Mul-vs-div gap <= ~2.5 ulp (~7.6e-5 abs at q<=256), so all
// non-boundary elements are guaranteed identical; boundary elements
// (~4e-4 of all) take one divide each.
// ---------------------------------------------------------------------------
__device__ __forceinline__ float quant1(float x, float mn, float step, float inv) {
    float d = x - mn;                 // >= 0 exactly
    float q = d * inv;
    float t = floorf(q);
    float frac = q - t;
    if (frac < 2e-4f || frac > 0.9998f) {
        q = __fdiv_rn(d, step);       // exact IEEE divide, matches reference
        t = floorf(q);
    }
    t = fmaxf(t, 0.0f);
    t = fminf(t, 255.0f);
    return mn + (t + 0.5f) * step;
}

__device__ __forceinline__ float4 quant4(float4 v, float mn, float step, float inv) {
    float4 r;
    r.x = quant1(v.x, mn, step, inv);
    r.y = quant1(v.y, mn, step, inv);
    r.z = quant1(v.z, mn, step, inv);
    r.w = quant1(v.w, mn, step, inv);
    return r;
}

__global__ void __launch_bounds__(256)
quant_kernel(const float4* __restrict__ x4, float4* __restrict__ o4, int n4,
             const float* __restrict__ x, float* __restrict__ o, int n,
             int nparts) {
    // ---- Prologue: recover global min/max from partials ----
    float mn =  FLT_MAX;
    float mx = -FLT_MAX;
    for (int j = threadIdx.x; j < nparts; j += 256) {
        mn = fminf(mn, g_pmn[j]);
        mx = fmaxf(mx, g_pmx[j]);
    }
    #pragma unroll
    for (int o_ = 16; o_ > 0; o_ >>= 1) {
        mn = fminf(mn, __shfl_xor_sync(0xFFFFFFFFu, mn, o_));
        mx = fmaxf(mx, __shfl_xor_sync(0xFFFFFFFFu, mx, o_));
    }
    __shared__ float smn[8], smx[8];
    int w = threadIdx.x >> 5;
    int l = threadIdx.x & 31;
    if (l == 0) { smn[w] = mn; smx[w] = mx; }
    __syncthreads();
    // every thread folds the 8 warp results (cheap; avoids second broadcast)
    mn = smn[0]; mx = smx[0];
    #pragma unroll
    for (int j = 1; j < 8; j++) {
        mn = fminf(mn, smn[j]);
        mx = fmaxf(mx, smx[j]);
    }

    // Reference: step = (max - min) / 256 ; /256 is exact, so *(1/256) matches.
    float step = (mx - mn) * (1.0f / 256.0f);
    float inv  = __fdiv_rn(1.0f, step);

    const int stride = gridDim.x * blockDim.x;
    const int gtid = blockIdx.x * blockDim.x + threadIdx.x;

    // Batched main loop: 4 independent LDG.128 in flight per iteration.
    int i = gtid;
    for (; i + 3 * stride < n4; i += 4 * stride) {
        float4 a = __ldcs(&x4[i]);
        float4 b = __ldcs(&x4[i + stride]);
        float4 c = __ldcs(&x4[i + 2 * stride]);
        float4 d = __ldcs(&x4[i + 3 * stride]);
        __stcs(&o4[i],              quant4(a, mn, step, inv));
        __stcs(&o4[i + stride],     quant4(b, mn, step, inv));
        __stcs(&o4[i + 2 * stride], quant4(c, mn, step, inv));
        __stcs(&o4[i + 3 * stride], quant4(d, mn, step, inv));
    }
    for (; i < n4; i += stride) {
        __stcs(&o4[i], quant4(__ldcs(&x4[i]), mn, step, inv));
    }
    int base = n4 << 2;
    if (gtid < (n - base)) {
        o[base + gtid] = quant1(x[base + gtid], mn, step, inv);
    }
}

// ---------------------------------------------------------------------------
// Launch
// ---------------------------------------------------------------------------
extern "C" void kernel_launch(void* const* d_in, const int* in_sizes, int n_in,
                              void* d_out, int out_size) {
    const float* x = (const float*)d_in[0];
    float* out = (float*)d_out;
    const int n  = in_sizes[0];
    const int n4 = n >> 2;

    const int threads = 256;
    int blocks = (n4 + threads - 1) / threads;
    if (blocks < 1) blocks = 1;
    int blocks_r = blocks > MAX_PARTIALS ? MAX_PARTIALS : blocks;   // 148*8
    int blocks_q = blocks > 2368 ? 2368 : blocks;                   // 148*16

    mm_reduce_kernel<<<blocks_r, threads>>>((const float4*)x, n4, x, n);
    quant_kernel<<<blocks_q, threads>>>((const float4*)x, (float4*)out, n4,
                                        x, out, n, blocks_r);
}

// round 6
// speedup vs baseline: 1.1007x; 1.0698x over previous
#include <cuda_runtime.h>
#include <float.h>

// ---------------------------------------------------------------------------
// Fused single-kernel quantizer:
//   phase 1: grid-stride min/max reduce (evict-normal loads -> populate L2)
//   grid barrier (generation-ticket; no reset needed -> graph-replay safe)
//   phase 2: quantize-dequantize, REVERSE order (reuse L2-hot tail), __stcs out
// ---------------------------------------------------------------------------
#define NBLOCKS 592                // 148 SMs * 4 CTAs, co-resident by construction
__device__ float g_pmn[NBLOCKS];
__device__ float g_pmx[NBLOCKS];
__device__ unsigned int g_arrive;  // monotonically increasing ticket counter

__device__ __forceinline__ float quant1(float x, float mn, float step, float inv) {
    float d = x - mn;                 // >= 0 exactly
    float q = d * inv;
    float t = floorf(q);
    float frac = q - t;
    if (frac < 2e-4f || frac > 0.9998f) {
        q = __fdiv_rn(d, step);       // exact IEEE divide, matches reference
        t = floorf(q);
    }
    t = fmaxf(t, 0.0f);
    t = fminf(t, 255.0f);
    return mn + (t + 0.5f) * step;
}

__device__ __forceinline__ float4 quant4(float4 v, float mn, float step, float inv) {
    float4 r;
    r.x = quant1(v.x, mn, step, inv);
    r.y = quant1(v.y, mn, step, inv);
    r.z = quant1(v.z, mn, step, inv);
    r.w = quant1(v.w, mn, step, inv);
    return r;
}

__global__ void __launch_bounds__(256, 4)
fused_quant_kernel(const float4* __restrict__ x4, float4* __restrict__ o4, int n4,
                   const float* __restrict__ x, float* __restrict__ o, int n) {
    const int stride = gridDim.x * blockDim.x;
    const int gtid = blockIdx.x * blockDim.x + threadIdx.x;
    const int G = gridDim.x;

    // ===================== Phase 1: min/max reduce ==========================
    float mn =  FLT_MAX;
    float mx = -FLT_MAX;

    int i = gtid;
    for (; i + 3 * stride < n4; i += 4 * stride) {
        float4 a = x4[i];
        float4 b = x4[i + stride];
        float4 c = x4[i + 2 * stride];
        float4 d = x4[i + 3 * stride];
        mn = fminf(mn, fminf(fminf(a.x, a.y), fminf(a.z, a.w)));
        mx = fmaxf(mx, fmaxf(fmaxf(a.x, a.y), fmaxf(a.z, a.w)));
        mn = fminf(mn, fminf(fminf(b.x, b.y), fminf(b.z, b.w)));
        mx = fmaxf(mx, fmaxf(fmaxf(b.x, b.y), fmaxf(b.z, b.w)));
        mn = fminf(mn, fminf(fminf(c.x, c.y), fminf(c.z, c.w)));
        mx = fmaxf(mx, fmaxf(fmaxf(c.x, c.y), fmaxf(c.z, c.w)));
        mn = fminf(mn, fminf(fminf(d.x, d.y), fminf(d.z, d.w)));
        mx = fmaxf(mx, fmaxf(fmaxf(d.x, d.y), fmaxf(d.z, d.w)));
    }
    for (; i < n4; i += stride) {
        float4 v = x4[i];
        mn = fminf(mn, fminf(fminf(v.x, v.y), fminf(v.z, v.w)));
        mx = fmaxf(mx, fmaxf(fmaxf(v.x, v.y), fmaxf(v.z, v.w)));
    }
    int base = n4 << 2;
    if (gtid < (n - base)) {            // scalar tail (n % 4 != 0)
        float v = x[base + gtid];
        mn = fminf(mn, v);
        mx = fmaxf(mx, v);
    }

    // Block reduce
    #pragma unroll
    for (int o_ = 16; o_ > 0; o_ >>= 1) {
        mn = fminf(mn, __shfl_xor_sync(0xFFFFFFFFu, mn, o_));
        mx = fmaxf(mx, __shfl_xor_sync(0xFFFFFFFFu, mx, o_));
    }
    __shared__ float smn[8], smx[8];
    int w = threadIdx.x >> 5;
    int l = threadIdx.x & 31;
    if (l == 0) { smn[w] = mn; smx[w] = mx; }
    __syncthreads();
    if (w == 0) {
        mn = (l < 8) ? smn[l] :  FLT_MAX;
        mx = (l < 8) ? smx[l] : -FLT_MAX;
        #pragma unroll
        for (int o_ = 4; o_ > 0; o_ >>= 1) {
            mn = fminf(mn, __shfl_xor_sync(0xFFFFFFFFu, mn, o_));
            mx = fmaxf(mx, __shfl_xor_sync(0xFFFFFFFFu, mx, o_));
        }
        if (l == 0) {
            g_pmn[blockIdx.x] = mn;
            g_pmx[blockIdx.x] = mx;
        }
    }

    // ===================== Grid barrier (generation ticket) =================
    // All NBLOCKS CTAs are co-resident (launch_bounds occupancy 4), so the
    // spin cannot deadlock. Counter is monotonic: replay k waits for k*G
    // arrivals -> no reset needed, deterministic across graph replays.
    if (threadIdx.x == 0) {
        __threadfence();                               // publish partials
        unsigned int ticket = atomicAdd(&g_arrive, 1u);
        unsigned int target = (ticket / G + 1u) * G;   // end of this generation
        while (*(volatile unsigned int*)&g_arrive < target) {
            __nanosleep(64);
        }
        __threadfence();                               // acquire partials
    }
    __syncthreads();

    // ===================== Fold partials (every block) ======================
    mn =  FLT_MAX;
    mx = -FLT_MAX;
    for (int j = threadIdx.x; j < G; j += 256) {
        mn = fminf(mn, g_pmn[j]);
        mx = fmaxf(mx, g_pmx[j]);
    }
    #pragma unroll
    for (int o_ = 16; o_ > 0; o_ >>= 1) {
        mn = fminf(mn, __shfl_xor_sync(0xFFFFFFFFu, mn, o_));
        mx = fmaxf(mx, __shfl_xor_sync(0xFFFFFFFFu, mx, o_));
    }
    __syncthreads();                    // smn/smx reuse
    if (l == 0) { smn[w] = mn; smx[w] = mx; }
    __syncthreads();
    mn = smn[0]; mx = smx[0];
    #pragma unroll
    for (int j = 1; j < 8; j++) {
        mn = fminf(mn, smn[j]);
        mx = fmaxf(mx, smx[j]);
    }

    // step = (max - min)/256 exactly (power-of-2 scale)
    float step = (mx - mn) * (1.0f / 256.0f);
    float inv  = __fdiv_rn(1.0f, step);

    // ===================== Phase 2: quantize (reverse order) ================
    // Walk indices from high to low so the tail of phase 1 (still L2-hot)
    // is consumed before the output stream can evict it.
    if (gtid < (n - base)) {
        o[base + gtid] = quant1(x[base + gtid], mn, step, inv);
    }
    if (gtid < n4) {
        int k = (n4 - 1 - gtid) / stride;      // highest iteration index
        for (; k >= 3; k -= 4) {
            int i0 = gtid + (k - 3) * stride;
            float4 a = x4[i0];
            float4 b = x4[i0 + stride];
            float4 c = x4[i0 + 2 * stride];
            float4 d = x4[i0 + 3 * stride];
            __stcs(&o4[i0],              quant4(a, mn, step, inv));
            __stcs(&o4[i0 + stride],     quant4(b, mn, step, inv));
            __stcs(&o4[i0 + 2 * stride], quant4(c, mn, step, inv));
            __stcs(&o4[i0 + 3 * stride], quant4(d, mn, step, inv));
        }
        for (; k >= 0; k--) {
            int i0 = gtid + k * stride;
            __stcs(&o4[i0], quant4(x4[i0], mn, step, inv));
        }
    }
}

// ---------------------------------------------------------------------------
// Launch
// ---------------------------------------------------------------------------
extern "C" void kernel_launch(void* const* d_in, const int* in_sizes, int n_in,
                              void* d_out, int out_size) {
    const float* x = (const float*)d_in[0];
    float* out = (float*)d_out;
    const int n  = in_sizes[0];
    const int n4 = n >> 2;

    fused_quant_kernel<<<NBLOCKS, 256>>>((const float4*)x, (float4*)out, n4,
                                         x, out, n);
}

// round 8
// speedup vs baseline: 1.1013x; 1.0005x over previous
#include <cuda_runtime.h>
#include <float.h>

// ---------------------------------------------------------------------------
// Fused single-kernel quantizer:
//   phase 1: grid-stride min/max reduce (evict-normal loads -> populate L2)
//   grid barrier (generation-ticket; no reset needed -> graph-replay safe)
//   phase 2: quantize-dequantize, REVERSE order (reuse L2-hot tail), __stcs out
// R7: occupancy 4 -> 6 CTAs/SM (48% -> ~75%) to hide DRAM latency; R6 ncu
// showed DRAM=57.5%, issue=30% with occ capped at 48.4% by launch bounds.
// ---------------------------------------------------------------------------
#define CTAS_PER_SM 6
#define NBLOCKS (148 * CTAS_PER_SM)    // co-resident by construction (888)
__device__ float g_pmn[NBLOCKS];
__device__ float g_pmx[NBLOCKS];
__device__ unsigned int g_arrive;      // monotonically increasing ticket counter

__device__ __forceinline__ float quant1(float x, float mn, float step, float inv) {
    float d = x - mn;                 // >= 0 exactly
    float q = d * inv;
    float t = floorf(q);
    float frac = q - t;
    if (frac < 2e-4f || frac > 0.9998f) {
        q = __fdiv_rn(d, step);       // exact IEEE divide, matches reference
        t = floorf(q);
    }
    t = fmaxf(t, 0.0f);
    t = fminf(t, 255.0f);
    return mn + (t + 0.5f) * step;
}

__device__ __forceinline__ float4 quant4(float4 v, float mn, float step, float inv) {
    float4 r;
    r.x = quant1(v.x, mn, step, inv);
    r.y = quant1(v.y, mn, step, inv);
    r.z = quant1(v.z, mn, step, inv);
    r.w = quant1(v.w, mn, step, inv);
    return r;
}

__global__ void __launch_bounds__(256, CTAS_PER_SM)
fused_quant_kernel(const float4* __restrict__ x4, float4* __restrict__ o4, int n4,
                   const float* __restrict__ x, float* __restrict__ o, int n) {
    const int stride = gridDim.x * blockDim.x;
    const int gtid = blockIdx.x * blockDim.x + threadIdx.x;
    const int G = gridDim.x;

    // ===================== Phase 1: min/max reduce ==========================
    float mn =  FLT_MAX;
    float mx = -FLT_MAX;

    int i = gtid;
    for (; i + 3 * stride < n4; i += 4 * stride) {
        float4 a = x4[i];
        float4 b = x4[i + stride];
        float4 c = x4[i + 2 * stride];
        float4 d = x4[i + 3 * stride];
        mn = fminf(mn, fminf(fminf(a.x, a.y), fminf(a.z, a.w)));
        mx = fmaxf(mx, fmaxf(fmaxf(a.x, a.y), fmaxf(a.z, a.w)));
        mn = fminf(mn, fminf(fminf(b.x, b.y), fminf(b.z, b.w)));
        mx = fmaxf(mx, fmaxf(fmaxf(b.x, b.y), fmaxf(b.z, b.w)));
        mn = fminf(mn, fminf(fminf(c.x, c.y), fminf(c.z, c.w)));
        mx = fmaxf(mx, fmaxf(fmaxf(c.x, c.y), fmaxf(c.z, c.w)));
        mn = fminf(mn, fminf(fminf(d.x, d.y), fminf(d.z, d.w)));
        mx = fmaxf(mx, fmaxf(fmaxf(d.x, d.y), fmaxf(d.z, d.w)));
    }
    #pragma unroll 1
    for (; i < n4; i += stride) {
        float4 v = x4[i];
        mn = fminf(mn, fminf(fminf(v.x, v.y), fminf(v.z, v.w)));
        mx = fmaxf(mx, fmaxf(fmaxf(v.x, v.y), fmaxf(v.z, v.w)));
    }
    int base = n4 << 2;
    if (gtid < (n - base)) {            // scalar tail (n % 4 != 0)
        float v = x[base + gtid];
        mn = fminf(mn, v);
        mx = fmaxf(mx, v);
    }

    // Block reduce
    #pragma unroll
    for (int o_ = 16; o_ > 0; o_ >>= 1) {
        mn = fminf(mn, __shfl_xor_sync(0xFFFFFFFFu, mn, o_));
        mx = fmaxf(mx, __shfl_xor_sync(0xFFFFFFFFu, mx, o_));
    }
    __shared__ float smn[8], smx[8];
    int w = threadIdx.x >> 5;
    int l = threadIdx.x & 31;
    if (l == 0) { smn[w] = mn; smx[w] = mx; }
    __syncthreads();
    if (w == 0) {
        mn = (l < 8) ? smn[l] :  FLT_MAX;
        mx = (l < 8) ? smx[l] : -FLT_MAX;
        #pragma unroll
        for (int o_ = 4; o_ > 0; o_ >>= 1) {
            mn = fminf(mn, __shfl_xor_sync(0xFFFFFFFFu, mn, o_));
            mx = fmaxf(mx, __shfl_xor_sync(0xFFFFFFFFu, mx, o_));
        }
        if (l == 0) {
            g_pmn[blockIdx.x] = mn;
            g_pmx[blockIdx.x] = mx;
        }
    }

    // ===================== Grid barrier (generation ticket) =================
    // All NBLOCKS CTAs are co-resident (launch_bounds occupancy CTAS_PER_SM),
    // so the spin cannot deadlock. Counter is monotonic: replay k waits for
    // k*G arrivals -> no reset needed, deterministic across graph replays.
    if (threadIdx.x == 0) {
        __threadfence();                               // publish partials
        unsigned int ticket = atomicAdd(&g_arrive, 1u);
        unsigned int target = (ticket / G + 1u) * G;   // end of this generation
        while (*(volatile unsigned int*)&g_arrive < target) {
            __nanosleep(64);
        }
        __threadfence();                               // acquire partials
    }
    __syncthreads();

    // ===================== Fold partials (every block) ======================
    mn =  FLT_MAX;
    mx = -FLT_MAX;
    #pragma unroll 1
    for (int j = threadIdx.x; j < G; j += 256) {
        mn = fminf(mn, g_pmn[j]);
        mx = fmaxf(mx, g_pmx[j]);
    }
    #pragma unroll
    for (int o_ = 16; o_ > 0; o_ >>= 1) {
        mn = fminf(mn, __shfl_xor_sync(0xFFFFFFFFu, mn, o_));
        mx = fmaxf(mx, __shfl_xor_sync(0xFFFFFFFFu, mx, o_));
    }
    __syncthreads();                    // smn/smx reuse
    if (l == 0) { smn[w] = mn; smx[w] = mx; }
    __syncthreads();
    mn = smn[0]; mx = smx[0];
    #pragma unroll
    for (int j = 1; j < 8; j++) {
        mn = fminf(mn, smn[j]);
        mx = fmaxf(mx, smx[j]);
    }

    // step = (max - min)/256 exactly (power-of-2 scale)
    float step = (mx - mn) * (1.0f / 256.0f);
    float inv  = __fdiv_rn(1.0f, step);

    // ===================== Phase 2: quantize (reverse order) ================
    // Walk indices from high to low so the tail of phase 1 (still L2-hot)
    // is consumed before the output stream can evict it.
    if (gtid < (n - base)) {
        o[base + gtid] = quant1(x[base + gtid], mn, step, inv);
    }
    if (gtid < n4) {
        int k = (n4 - 1 - gtid) / stride;      // highest iteration index
        for (; k >= 3; k -= 4) {
            int i0 = gtid + (k - 3) * stride;
            float4 a = x4[i0];
            float4 b = x4[i0 + stride];
            float4 c = x4[i0 + 2 * stride];
            float4 d = x4[i0 + 3 * stride];
            __stcs(&o4[i0],              quant4(a, mn, step, inv));
            __stcs(&o4[i0 + stride],     quant4(b, mn, step, inv));
            __stcs(&o4[i0 + 2 * stride], quant4(c, mn, step, inv));
            __stcs(&o4[i0 + 3 * stride], quant4(d, mn, step, inv));
        }
        #pragma unroll 1
        for (; k >= 0; k--) {
            int i0 = gtid + k * stride;
            __stcs(&o4[i0], quant4(x4[i0], mn, step, inv));
        }
    }
}

// ---------------------------------------------------------------------------
// Launch
// ---------------------------------------------------------------------------
extern "C" void kernel_launch(void* const* d_in, const int* in_sizes, int n_in,
                              void* d_out, int out_size) {
    const float* x = (const float*)d_in[0];
    float* out = (float*)d_out;
    const int n  = in_sizes[0];
    const int n4 = n >> 2;

    fused_quant_kernel<<<NBLOCKS, 256>>>((const float4*)x, (float4*)out, n4,
                                         x, out, n);
}